// round 11
// baseline (speedup 1.0000x reference)
#include <cuda_runtime.h>
#include <cstdint>

#define T_TOK 4096
#define DIM   512
#define FDIM  2048
#define NEXP  8
#define EPSV  1e-8f

#define TM   128
#define TN   128
#define KC   32
#define NSTG 2
#define NGRP (NEXP * (T_TOK / TM))
#define XT_STRIDE ((DIM / KC) * 16 * 128)
#define HT_STRIDE ((FDIM / KC) * 16 * 128)

#if defined(__CUDA_ARCH__) && defined(__CUDA_ARCH_FEAT_SM103_ALL)
#define USE_TC 1
#else
#define USE_TC 0
#endif

#define SMEM_STAGE 32768            // [A hi 8K][A lo 8K][B hi 8K][B lo 8K]
#define SMEM_DYN   (NSTG * SMEM_STAGE + 1024)
#define NTHREADS   288

// -------- scratch --------
__device__ float    g_anchors_n[NEXP * DIM];
__device__ int      g_cnt[NEXP];
__device__ int      g_tok[NEXP][T_TOK];
__device__ float    g_gate[NEXP][T_TOK];
__device__ uint32_t g_Xhi[T_TOK * (DIM / 2)];
__device__ uint32_t g_Xlo[T_TOK * (DIM / 2)];
__device__ uint32_t g_XThi[NGRP * XT_STRIDE];
__device__ uint32_t g_XTlo[NGRP * XT_STRIDE];
__device__ uint32_t g_HThi[(size_t)NGRP * HT_STRIDE];
__device__ uint32_t g_HTlo[(size_t)NGRP * HT_STRIDE];
__device__ float    g_H[(2 * T_TOK) * FDIM];   // fallback only

// ==================== helpers ====================
__device__ __forceinline__ float gelu_f(float h) {
    return 0.5f * h * (1.f + erff(h * 0.7071067811865476f));
}
__device__ __forceinline__ void split2_bf16(float v0, float v1, uint32_t& hw, uint32_t& lw) {
    asm("cvt.rn.satfinite.bf16x2.f32 %0, %1, %2;" : "=r"(hw) : "f"(v1), "f"(v0));
    float h0 = __uint_as_float(hw << 16);
    float h1 = __uint_as_float(hw & 0xffff0000u);
    asm("cvt.rn.satfinite.bf16x2.f32 %0, %1, %2;" : "=r"(lw) : "f"(v1 - h1), "f"(v0 - h0));
}
__device__ __forceinline__ unsigned long long pack2(float a) {
    unsigned long long r;
    asm("mov.b64 %0, {%1, %1};" : "=l"(r) : "f"(a));
    return r;
}
__device__ __forceinline__ unsigned long long fma2(unsigned long long a,
                                                   unsigned long long b,
                                                   unsigned long long c) {
    unsigned long long d;
    asm("fma.rn.f32x2 %0, %1, %2, %3;" : "=l"(d) : "l"(a), "l"(b), "l"(c));
    return d;
}
__device__ __forceinline__ void ld16(uint32_t* dst, const uint32_t* src) {
    #pragma unroll
    for (int i = 0; i < 4; i++) {
        uint4 v = ((const uint4*)src)[i];
        dst[4 * i + 0] = v.x; dst[4 * i + 1] = v.y;
        dst[4 * i + 2] = v.z; dst[4 * i + 3] = v.w;
    }
}

#if USE_TC
__device__ __forceinline__ uint32_t sm2u32(const void* p) {
    uint32_t a;
    asm("{ .reg .u64 t; cvta.to.shared.u64 t, %1; cvt.u32.u64 %0, t; }" : "=r"(a) : "l"(p));
    return a;
}
__device__ __forceinline__ bool elect1() {
    uint32_t r;
    asm volatile("{ .reg .pred p; elect.sync _|p, 0xFFFFFFFF; selp.b32 %0, 1, 0, p; }" : "=r"(r));
    return r != 0;
}
__device__ __forceinline__ void sts128u(uint32_t a, const uint32_t* w) {
    asm volatile("st.shared.v4.b32 [%0], {%1,%2,%3,%4};"
                 :: "r"(a), "r"(w[0]), "r"(w[1]), "r"(w[2]), "r"(w[3]) : "memory");
}
__device__ __forceinline__ void mbar_init(uint32_t a, uint32_t c) {
    asm volatile("mbarrier.init.shared.b64 [%0], %1;" :: "r"(a), "r"(c) : "memory");
}
__device__ __forceinline__ void mbar_inval(uint32_t a) {
    asm volatile("mbarrier.inval.shared.b64 [%0];" :: "r"(a) : "memory");
}
__device__ __forceinline__ void mbar_arrive(uint32_t a) {
    asm volatile("mbarrier.arrive.shared.b64 _, [%0];" :: "r"(a) : "memory");
}
__device__ __forceinline__ void mbar_wait(uint32_t a, uint32_t ph) {
    uint32_t done;
    asm volatile("{\n\t.reg .pred p;\n\t"
                 "mbarrier.try_wait.parity.acquire.cta.shared::cta.b64 p, [%1], %2;\n\t"
                 "selp.b32 %0, 1, 0, p;\n\t}"
                 : "=r"(done) : "r"(a), "r"(ph) : "memory");
    if (!done) {
        asm volatile("{\n\t.reg .pred P1;\n\t"
                     "LW%=:\n\t"
                     "mbarrier.try_wait.parity.acquire.cta.shared::cta.b64 P1, [%0], %1, 0x989680;\n\t"
                     "@P1 bra.uni LD%=;\n\t"
                     "bra.uni LW%=;\n\t"
                     "LD%=:\n\t}"
                     :: "r"(a), "r"(ph) : "memory");
    }
}
__device__ __forceinline__ void tc_commit(uint32_t mb) {
    asm volatile("tcgen05.commit.cta_group::1.mbarrier::arrive::one.shared::cluster.b64 [%0];"
                 :: "r"(mb) : "memory");
}
// SS-mode: both operands from SMEM descriptors
__device__ __forceinline__ void mma_f16_ss(uint32_t d, uint64_t a, uint64_t b,
                                           uint32_t idesc, uint32_t en) {
    asm volatile("{\n\t.reg .pred p;\n\tsetp.ne.u32 p, %4, 0;\n\t"
                 "tcgen05.mma.cta_group::1.kind::f16 [%0], %1, %2, %3, {%5,%5,%5,%5}, p;\n\t}"
                 :: "r"(d), "l"(a), "l"(b), "r"(idesc), "r"(en), "r"(0u) : "memory");
}
#define LDTM32(r, ta) \
    asm volatile( \
        "tcgen05.ld.sync.aligned.32x32b.x32.b32 " \
        "{%0, %1, %2, %3, %4, %5, %6, %7, " \
        " %8, %9, %10, %11, %12, %13, %14, %15, " \
        " %16, %17, %18, %19, %20, %21, %22, %23, " \
        " %24, %25, %26, %27, %28, %29, %30, %31}, [%32];" \
        : "=r"((r)[0]),  "=r"((r)[1]),  "=r"((r)[2]),  "=r"((r)[3]), \
          "=r"((r)[4]),  "=r"((r)[5]),  "=r"((r)[6]),  "=r"((r)[7]), \
          "=r"((r)[8]),  "=r"((r)[9]),  "=r"((r)[10]), "=r"((r)[11]), \
          "=r"((r)[12]), "=r"((r)[13]), "=r"((r)[14]), "=r"((r)[15]), \
          "=r"((r)[16]), "=r"((r)[17]), "=r"((r)[18]), "=r"((r)[19]), \
          "=r"((r)[20]), "=r"((r)[21]), "=r"((r)[22]), "=r"((r)[23]), \
          "=r"((r)[24]), "=r"((r)[25]), "=r"((r)[26]), "=r"((r)[27]), \
          "=r"((r)[28]), "=r"((r)[29]), "=r"((r)[30]), "=r"((r)[31]) \
        : "r"(ta))

__device__ __forceinline__ uint64_t mk_desc64(uint32_t addr) {
    return ((uint64_t)4 << 61) | ((uint64_t)1 << 46) | ((uint64_t)32 << 32) |
           ((uint64_t)1 << 16) | ((uint64_t)(addr >> 4) & 0x3FFF);
}
__device__ __forceinline__ uint32_t swoff64(int r, int c16) {
    return (uint32_t)(((r >> 3) << 9) + ((r & 7) << 6) + (((c16 ^ ((r >> 1) & 3)) & 3) << 4));
}
#define IDESC_BF ((1u << 4) | (1u << 7) | (1u << 10) | ((TN / 8) << 17) | ((TM / 16) << 24))
#define TMEM_NCOLS 128
#define TM_D 0

// ---- A producer: copy transposed planes -> SW64 smem (no cvt) ----
#define A_COPY(cc) do { \
    const int st_ = (cc) & (NSTG - 1); \
    if ((cc) >= NSTG) { \
        if (lane == 0) mbar_wait(mb_done + st_ * 8, (((cc) >> 1) + 1) & 1); \
        __syncwarp(); \
    } \
    const uint32_t Ah_ = sm + st_ * SMEM_STAGE; \
    const uint32_t Al_ = Ah_ + 8192; \
    _Pragma("unroll") \
    for (int q_ = 0; q_ < 4; q_++) { \
        uint32_t w_[4]; \
        _Pragma("unroll") \
        for (int i_ = 0; i_ < 4; i_++) w_[i_] = rhi[(size_t)(cc) * 2048 + (4 * q_ + i_) * 128]; \
        sts128u(Ah_ + swoff64(row, q_), w_); \
        _Pragma("unroll") \
        for (int i_ = 0; i_ < 4; i_++) w_[i_] = rlo[(size_t)(cc) * 2048 + (4 * q_ + i_) * 128]; \
        sts128u(Al_ + swoff64(row, q_), w_); \
    } \
    asm volatile("fence.proxy.async.shared::cta;" ::: "memory"); \
    __syncwarp(); \
    if (lane == 0) mbar_arrive(mb_full + st_ * 8); \
} while (0)

// ---- B producer: fp32 -> bf16 hi/lo, processed in two 16-k halves ----
#define B_CONV(cc) do { \
    const int st_ = (cc) & (NSTG - 1); \
    if ((cc) >= NSTG) { \
        if (lane == 0) mbar_wait(mb_done + st_ * 8, (((cc) >> 1) + 1) & 1); \
        __syncwarp(); \
    } \
    const uint32_t Bh_ = sm + st_ * SMEM_STAGE + 16384; \
    const uint32_t Bl_ = Bh_ + 8192; \
    _Pragma("unroll") \
    for (int h_ = 0; h_ < 2; h_++) { \
        float fb_[16]; \
        _Pragma("unroll") \
        for (int k_ = 0; k_ < 16; k_++) \
            fb_[k_] = wp[(size_t)((cc) * KC + h_ * 16 + k_) * wld]; \
        uint32_t hw_[8], lw_[8]; \
        _Pragma("unroll") \
        for (int i_ = 0; i_ < 8; i_++) \
            split2_bf16(fb_[2 * i_], fb_[2 * i_ + 1], hw_[i_], lw_[i_]); \
        sts128u(Bh_ + swoff64(n, 2 * h_),     hw_); \
        sts128u(Bh_ + swoff64(n, 2 * h_ + 1), hw_ + 4); \
        sts128u(Bl_ + swoff64(n, 2 * h_),     lw_); \
        sts128u(Bl_ + swoff64(n, 2 * h_ + 1), lw_ + 4); \
    } \
    asm volatile("fence.proxy.async.shared::cta;" ::: "memory"); \
    __syncwarp(); \
    if (lane == 0) mbar_arrive(mb_full + st_ * 8); \
} while (0)
#endif  // USE_TC

// ==================== small kernels ====================
__global__ void k_anchors(const float* __restrict__ A, float* __restrict__ an_out,
                          int write_an) {
    int w = threadIdx.x >> 5, lane = threadIdx.x & 31;
    if (threadIdx.x < NEXP) g_cnt[threadIdx.x] = 0;
    float ss = 0.f;
    for (int d = lane; d < DIM; d += 32) { float v = A[w * DIM + d]; ss += v * v; }
    #pragma unroll
    for (int o = 16; o; o >>= 1) ss += __shfl_xor_sync(0xffffffffu, ss, o);
    float inv = 1.f / fmaxf(sqrtf(ss), EPSV);
    for (int d = lane; d < DIM; d += 32) {
        float v = A[w * DIM + d] * inv;
        g_anchors_n[w * DIM + d] = v;
        if (write_an) an_out[w * DIM + d] = v;
    }
}

__global__ void k_route(const float* __restrict__ x, float* __restrict__ out,
                        float* __restrict__ scores_out,
                        float* __restrict__ idx_out, int wflags) {
    {
        int t = blockIdx.x * blockDim.x + threadIdx.x;
        float4* o4 = (float4*)out;
        #pragma unroll
        for (int j = 0; j < 4; j++)
            o4[t * 4 + j] = make_float4(0.f, 0.f, 0.f, 0.f);
    }
    int wid = (blockIdx.x * blockDim.x + threadIdx.x) >> 5;
    int lane = threadIdx.x & 31;
    if (wid >= T_TOK) return;
    const float* xr = x + (size_t)wid * DIM;
    float xx = 0.f;
    float dt[NEXP];
    #pragma unroll
    for (int e = 0; e < NEXP; e++) dt[e] = 0.f;
    #pragma unroll
    for (int j = 0; j < 8; j++) {
        int d0 = lane * 2 + j * 64;
        float v0 = xr[d0], v1 = xr[d0 + 1];
        xx += v0 * v0 + v1 * v1;
        #pragma unroll
        for (int e = 0; e < NEXP; e++)
            dt[e] += v0 * g_anchors_n[e * DIM + d0] + v1 * g_anchors_n[e * DIM + d0 + 1];
        uint32_t hw, lw;
        split2_bf16(v0, v1, hw, lw);
        g_Xhi[(size_t)wid * (DIM / 2) + lane + j * 32] = hw;
        g_Xlo[(size_t)wid * (DIM / 2) + lane + j * 32] = lw;
    }
    #pragma unroll
    for (int o = 16; o; o >>= 1) {
        xx += __shfl_xor_sync(0xffffffffu, xx, o);
        #pragma unroll
        for (int e = 0; e < NEXP; e++) dt[e] += __shfl_xor_sync(0xffffffffu, dt[e], o);
    }
    if (lane == 0) {
        float inv = 1.f / fmaxf(sqrtf(xx), EPSV);
        float s[NEXP];
        #pragma unroll
        for (int e = 0; e < NEXP; e++) s[e] = dt[e] * inv;
        int i1 = 0; float v1 = s[0];
        #pragma unroll
        for (int e = 1; e < NEXP; e++) if (s[e] > v1) { v1 = s[e]; i1 = e; }
        int i2 = -1; float v2 = -1e30f;
        #pragma unroll
        for (int e = 0; e < NEXP; e++) if (e != i1 && s[e] > v2) { v2 = s[e]; i2 = e; }
        float e2 = expf(v2 - v1);
        float denom = 1.f / (1.f + e2);
        float g1 = denom, g2 = e2 * denom;
        int s1 = atomicAdd(&g_cnt[i1], 1);
        g_tok[i1][s1] = wid; g_gate[i1][s1] = g1;
        int s2 = atomicAdd(&g_cnt[i2], 1);
        g_tok[i2][s2] = wid; g_gate[i2][s2] = g2;
        if (wflags & 1) {
            #pragma unroll
            for (int e = 0; e < NEXP; e++) scores_out[wid * NEXP + e] = s[e];
        }
        if (wflags & 2) {
            idx_out[wid * 2 + 0] = (float)i1;
            idx_out[wid * 2 + 1] = (float)i2;
        }
    }
}

__global__ void k_xpose() {
    const int e = blockIdx.y, mt = blockIdx.x;
    const int count = g_cnt[e];
    const int m0 = mt * TM;
    if (m0 >= count) return;
    const int gid = e * (T_TOK / TM) + mt;
    const int tid = threadIdx.x;
    const int tok = g_tok[e][min(m0 + tid, count - 1)];
    const uint32_t* rhi = g_Xhi + (size_t)tok * (DIM / 2);
    const uint32_t* rlo = g_Xlo + (size_t)tok * (DIM / 2);
    uint32_t* dhi = g_XThi + (size_t)gid * XT_STRIDE;
    uint32_t* dlo = g_XTlo + (size_t)gid * XT_STRIDE;
    for (int c = 0; c < DIM / KC; c++) {
        uint32_t h[16], l[16];
        ld16(h, rhi + c * 16);
        ld16(l, rlo + c * 16);
        #pragma unroll
        for (int j = 0; j < 16; j++) {
            dhi[c * 2048 + j * 128 + tid] = h[j];
            dlo[c * 2048 + j * 128 + tid] = l[j];
        }
    }
}

#if USE_TC
// shared SS-mode MMA issuer loop
__device__ __forceinline__ void mma_loop(int NC, uint32_t sm, uint32_t tmem,
                                         uint32_t mb_done, uint32_t mb_full) {
    if (elect1()) {
        for (int c = 0; c < NC; c++) {
            const int st = c & (NSTG - 1);
            mbar_wait(mb_full + st * 8, (c >> 1) & 1);
            const uint32_t base = sm + st * SMEM_STAGE;
            uint64_t dAh = mk_desc64(base), dAl = mk_desc64(base + 8192);
            uint64_t dBh = mk_desc64(base + 16384), dBl = mk_desc64(base + 24576);
            #pragma unroll
            for (int s2 = 0; s2 < 2; s2++) {
                mma_f16_ss(tmem + TM_D, dAh + s2 * 2, dBh + s2 * 2, IDESC_BF,
                           (c | s2) ? 1u : 0u);
                mma_f16_ss(tmem + TM_D, dAh + s2 * 2, dBl + s2 * 2, IDESC_BF, 1u);
                mma_f16_ss(tmem + TM_D, dAl + s2 * 2, dBh + s2 * 2, IDESC_BF, 1u);
            }
            tc_commit(mb_done + st * 8);
        }
    }
}
#endif

// ==================== GEMM1 ====================
__global__ __launch_bounds__(NTHREADS, 3)
void k_gemm1(const float* __restrict__ x, const float* __restrict__ W1,
             const float* __restrict__ b1) {
    const int e = blockIdx.z;
    const int count = g_cnt[e];
    const int m0 = blockIdx.y * TM;
    if (m0 >= count) return;
    const int n0 = blockIdx.x * TN;
    const int gid = e * (T_TOK / TM) + blockIdx.y;
    const int tid = threadIdx.x;
    const int wid = tid >> 5, lane = tid & 31;
    extern __shared__ char dynraw[];
    __shared__ int toks[TM];
    if (tid < TM) toks[tid] = g_tok[e][min(m0 + tid, count - 1)];

#if USE_TC
    __shared__ __align__(8) unsigned long long s_bar[2 * NSTG];
    __shared__ uint32_t s_tmem;
    const uint32_t sm = (sm2u32(dynraw) + 1023u) & ~1023u;
    if (tid == 0) {
        for (int s = 0; s < NSTG; s++) {
            mbar_init(sm2u32(&s_bar[s]), 1);
            mbar_init(sm2u32(&s_bar[NSTG + s]), 8);
        }
    }
    if (wid == 0) {
        asm volatile("tcgen05.alloc.cta_group::1.sync.aligned.shared::cta.b32 [%0], %1;"
                     :: "r"(sm2u32(&s_tmem)), "r"((uint32_t)TMEM_NCOLS) : "memory");
        asm volatile("tcgen05.relinquish_alloc_permit.cta_group::1.sync.aligned;");
    }
    __syncthreads();
    const uint32_t tmem = s_tmem;
    const uint32_t mb_done = sm2u32(&s_bar[0]);
    const uint32_t mb_full = sm2u32(&s_bar[NSTG]);
    const int NC = DIM / KC;   // 16

    if (wid < 4) {
        const int row = tid;
        const uint32_t* rhi = g_XThi + (size_t)gid * XT_STRIDE + row;
        const uint32_t* rlo = g_XTlo + (size_t)gid * XT_STRIDE + row;
        for (int c = 0; c < NC; c++) A_COPY(c);
    } else if (wid < 8) {
        const int n = tid - 128;
        const float* wp = W1 + (size_t)e * DIM * FDIM + n0 + n;
        const int wld = FDIM;
        for (int c = 0; c < NC; c++) B_CONV(c);
    } else {
        mma_loop(NC, sm, tmem, mb_done, mb_full);
    }
    __syncthreads();
    mbar_wait(mb_done + ((NC - 1) & (NSTG - 1)) * 8, ((NC - 1) >> 1) & 1);
    asm volatile("tcgen05.fence::after_thread_sync;" ::: "memory");

    if (wid < 8) {
        const int sp = wid & 3, half = wid >> 2;
        const int ml = sp * 32 + lane;
        const int mi = m0 + ml;
        const bool valid = mi < count;
        uint32_t* dhi = g_HThi + (size_t)gid * HT_STRIDE;
        uint32_t* dlo = g_HTlo + (size_t)gid * HT_STRIDE;
        const float* bp = b1 + (size_t)e * FDIM + n0;
        #pragma unroll
        for (int cb = 0; cb < 2; cb++) {
            const uint32_t c0 = half * 64 + cb * 32;
            uint32_t rg[32];
            LDTM32(rg, tmem + TM_D + c0);
            asm volatile("tcgen05.wait::ld.sync.aligned;" ::: "memory");
            if (valid) {
                const int chunk = (n0 + (int)c0) >> 5;
                #pragma unroll
                for (int i = 0; i < 16; i++) {
                    float y0 = gelu_f(__uint_as_float(rg[2 * i + 0]) + bp[c0 + 2 * i + 0]);
                    float y1 = gelu_f(__uint_as_float(rg[2 * i + 1]) + bp[c0 + 2 * i + 1]);
                    uint32_t hw, lw;
                    split2_bf16(y0, y1, hw, lw);
                    dhi[(size_t)chunk * 2048 + i * 128 + ml] = hw;
                    dlo[(size_t)chunk * 2048 + i * 128 + ml] = lw;
                }
            }
        }
        asm volatile("tcgen05.fence::before_thread_sync;" ::: "memory");
    }
    __syncthreads();
    if (tid == 0)
        for (int s = 0; s < 2 * NSTG; s++) mbar_inval(sm2u32(&s_bar[s]));
    if (wid == 0) {
        asm volatile("tcgen05.dealloc.cta_group::1.sync.aligned.b32 %0, %1;"
                     :: "r"(tmem), "r"((uint32_t)TMEM_NCOLS));
    }
#else
    // ---------- FFMA f32x2 fallback (tid<256 active) ----------
    __shared__ int s_base;
    if (tid == 0) {
        int b = 0;
        for (int i = 0; i < e; i++) b += g_cnt[i];
        s_base = b;
    }
    float* As = (float*)dynraw;
    float* Bs = As + 16 * 132;
    __syncthreads();
    const int base = s_base;
    const int tx = tid & 15, ty = tid >> 4;
    unsigned long long acc[8][4];
    #pragma unroll
    for (int i = 0; i < 8; i++)
        #pragma unroll
        for (int j = 0; j < 4; j++) acc[i][j] = 0ull;
    const float* Wb = W1 + (size_t)e * DIM * FDIM + n0;
    for (int k0 = 0; k0 < DIM; k0 += 16) {
        if (tid < 256) {
            #pragma unroll
            for (int j = 0; j < 2; j++) {
                int q = tid + j * 256;
                int m = q >> 2, kq = q & 3;
                float4 v = *(const float4*)(x + (size_t)toks[m] * DIM + k0 + kq * 4);
                As[(kq * 4 + 0) * 132 + m] = v.x; As[(kq * 4 + 1) * 132 + m] = v.y;
                As[(kq * 4 + 2) * 132 + m] = v.z; As[(kq * 4 + 3) * 132 + m] = v.w;
            }
            #pragma unroll
            for (int j = 0; j < 2; j++) {
                int q = tid + j * 256;
                int kk = q >> 5, nq = q & 31;
                float4 v = *(const float4*)(Wb + (size_t)(k0 + kk) * FDIM + nq * 4);
                *(float4*)&Bs[kk * 132 + nq * 4] = v;
            }
        }
        __syncthreads();
        if (tid < 256) {
            #pragma unroll
            for (int k = 0; k < 16; k++) {
                float4 a0 = *(float4*)&As[k * 132 + ty * 4];
                float4 a1 = *(float4*)&As[k * 132 + 64 + ty * 4];
                float4 b0 = *(float4*)&Bs[k * 132 + tx * 4];
                float4 b1r = *(float4*)&Bs[k * 132 + 64 + tx * 4];
                unsigned long long bb[4];
                bb[0] = ((const unsigned long long*)&b0)[0];
                bb[1] = ((const unsigned long long*)&b0)[1];
                bb[2] = ((const unsigned long long*)&b1r)[0];
                bb[3] = ((const unsigned long long*)&b1r)[1];
                float av[8] = {a0.x, a0.y, a0.z, a0.w, a1.x, a1.y, a1.z, a1.w};
                #pragma unroll
                for (int i = 0; i < 8; i++) {
                    unsigned long long aa = pack2(av[i]);
                    #pragma unroll
                    for (int jj = 0; jj < 4; jj++) acc[i][jj] = fma2(aa, bb[jj], acc[i][jj]);
                }
            }
        }
        __syncthreads();
    }
    if (tid < 256) {
        #pragma unroll
        for (int i = 0; i < 8; i++) {
            int mloc = (i < 4) ? (ty * 4 + i) : (64 + ty * 4 + (i - 4));
            int mi = m0 + mloc;
            if (mi >= count) continue;
            float* Hrow = g_H + (size_t)(base + mi) * FDIM + n0;
            #pragma unroll
            for (int jj = 0; jj < 4; jj++) {
                int nloc = (jj < 2) ? (tx * 4 + jj * 2) : (64 + tx * 4 + (jj - 2) * 2);
                float2 v = *(float2*)&acc[i][jj];
                float h0 = gelu_f(v.x + b1[e * FDIM + n0 + nloc]);
                float h1 = gelu_f(v.y + b1[e * FDIM + n0 + nloc + 1]);
                *(float2*)(Hrow + nloc) = make_float2(h0, h1);
            }
        }
    }
#endif
}

// ==================== GEMM2 ====================
__global__ __launch_bounds__(NTHREADS, 3)
void k_gemm2(const float* __restrict__ W2, const float* __restrict__ b2,
             float* __restrict__ out) {
    const int e = blockIdx.z;
    const int count = g_cnt[e];
    const int m0 = blockIdx.y * TM;
    if (m0 >= count) return;
    const int n0 = blockIdx.x * TN;
    const int gid = e * (T_TOK / TM) + blockIdx.y;
    const int tid = threadIdx.x;
    const int wid = tid >> 5, lane = tid & 31;
    extern __shared__ char dynraw[];
    __shared__ int   toks[TM];
    __shared__ float gts[TM];
    if (tid < TM) {
        int mi = min(m0 + tid, count - 1);
        toks[tid] = g_tok[e][mi];
        gts[tid]  = g_gate[e][mi];
    }

#if USE_TC
    __shared__ __align__(8) unsigned long long s_bar[2 * NSTG];
    __shared__ uint32_t s_tmem;
    const uint32_t sm = (sm2u32(dynraw) + 1023u) & ~1023u;
    if (tid == 0) {
        for (int s = 0; s < NSTG; s++) {
            mbar_init(sm2u32(&s_bar[s]), 1);
            mbar_init(sm2u32(&s_bar[NSTG + s]), 8);
        }
    }
    if (wid == 0) {
        asm volatile("tcgen05.alloc.cta_group::1.sync.aligned.shared::cta.b32 [%0], %1;"
                     :: "r"(sm2u32(&s_tmem)), "r"((uint32_t)TMEM_NCOLS) : "memory");
        asm volatile("tcgen05.relinquish_alloc_permit.cta_group::1.sync.aligned;");
    }
    __syncthreads();
    const uint32_t tmem = s_tmem;
    const uint32_t mb_done = sm2u32(&s_bar[0]);
    const uint32_t mb_full = sm2u32(&s_bar[NSTG]);
    const int NC = FDIM / KC;   // 64

    if (wid < 4) {
        const int row = tid;
        const uint32_t* rhi = g_HThi + (size_t)gid * HT_STRIDE + row;
        const uint32_t* rlo = g_HTlo + (size_t)gid * HT_STRIDE + row;
        for (int c = 0; c < NC; c++) A_COPY(c);
    } else if (wid < 8) {
        const int n = tid - 128;
        const float* wp = W2 + (size_t)e * FDIM * DIM + n0 + n;
        const int wld = DIM;
        for (int c = 0; c < NC; c++) B_CONV(c);
    } else {
        mma_loop(NC, sm, tmem, mb_done, mb_full);
    }
    __syncthreads();
    mbar_wait(mb_done + ((NC - 1) & (NSTG - 1)) * 8, ((NC - 1) >> 1) & 1);
    asm volatile("tcgen05.fence::after_thread_sync;" ::: "memory");

    if (wid < 8) {
        const int sp = wid & 3, half = wid >> 2;
        const int ml = sp * 32 + lane;
        const int mi = m0 + ml;
        const bool valid = mi < count;
        const int tok = toks[ml];
        const float gate = gts[ml];
        float* orow = out + (size_t)tok * DIM + n0;
        const float* bp = b2 + (size_t)e * DIM + n0;
        #pragma unroll
        for (int cb = 0; cb < 2; cb++) {
            const uint32_t c0 = half * 64 + cb * 32;
            uint32_t rg[32];
            LDTM32(rg, tmem + TM_D + c0);
            asm volatile("tcgen05.wait::ld.sync.aligned;" ::: "memory");
            if (valid) {
                #pragma unroll
                for (int i = 0; i < 32; i++) {
                    float y = __uint_as_float(rg[i]) + bp[c0 + i];
                    atomicAdd(orow + c0 + i, gate * y);
                }
            }
        }
        asm volatile("tcgen05.fence::before_thread_sync;" ::: "memory");
    }
    __syncthreads();
    if (tid == 0)
        for (int s = 0; s < 2 * NSTG; s++) mbar_inval(sm2u32(&s_bar[s]));
    if (wid == 0) {
        asm volatile("tcgen05.dealloc.cta_group::1.sync.aligned.b32 %0, %1;"
                     :: "r"(tmem), "r"((uint32_t)TMEM_NCOLS));
    }
#else
    // ---------- FFMA f32x2 fallback (tid<256 active) ----------
    __shared__ int s_base;
    if (tid == 0) {
        int b = 0;
        for (int i = 0; i < e; i++) b += g_cnt[i];
        s_base = b;
    }
    float* As = (float*)dynraw;
    float* Bs = As + 16 * 132;
    __syncthreads();
    const int base = s_base;
    const int tx = tid & 15, ty = tid >> 4;
    unsigned long long acc[8][4];
    #pragma unroll
    for (int i = 0; i < 8; i++)
        #pragma unroll
        for (int j = 0; j < 4; j++) acc[i][j] = 0ull;
    const float* Wb = W2 + (size_t)e * FDIM * DIM + n0;
    for (int k0 = 0; k0 < FDIM; k0 += 16) {
        if (tid < 256) {
            #pragma unroll
            for (int j = 0; j < 2; j++) {
                int q = tid + j * 256;
                int m = q >> 2, kq = q & 3;
                int rowg = base + min(m0 + m, count - 1);
                float4 v = *(const float4*)(g_H + (size_t)rowg * FDIM + k0 + kq * 4);
                As[(kq * 4 + 0) * 132 + m] = v.x; As[(kq * 4 + 1) * 132 + m] = v.y;
                As[(kq * 4 + 2) * 132 + m] = v.z; As[(kq * 4 + 3) * 132 + m] = v.w;
            }
            #pragma unroll
            for (int j = 0; j < 2; j++) {
                int q = tid + j * 256;
                int kk = q >> 5, nq = q & 31;
                float4 v = *(const float4*)(Wb + (size_t)(k0 + kk) * DIM + nq * 4);
                *(float4*)&Bs[kk * 132 + nq * 4] = v;
            }
        }
        __syncthreads();
        if (tid < 256) {
            #pragma unroll
            for (int k = 0; k < 16; k++) {
                float4 a0 = *(float4*)&As[k * 132 + ty * 4];
                float4 a1 = *(float4*)&As[k * 132 + 64 + ty * 4];
                float4 b0 = *(float4*)&Bs[k * 132 + tx * 4];
                float4 b1r = *(float4*)&Bs[k * 132 + 64 + tx * 4];
                unsigned long long bb[4];
                bb[0] = ((const unsigned long long*)&b0)[0];
                bb[1] = ((const unsigned long long*)&b0)[1];
                bb[2] = ((const unsigned long long*)&b1r)[0];
                bb[3] = ((const unsigned long long*)&b1r)[1];
                float av[8] = {a0.x, a0.y, a0.z, a0.w, a1.x, a1.y, a1.z, a1.w};
                #pragma unroll
                for (int i = 0; i < 8; i++) {
                    unsigned long long aa = pack2(av[i]);
                    #pragma unroll
                    for (int jj = 0; jj < 4; jj++) acc[i][jj] = fma2(aa, bb[jj], acc[i][jj]);
                }
            }
        }
        __syncthreads();
    }
    if (tid < 256) {
        #pragma unroll
        for (int i = 0; i < 8; i++) {
            int mloc = (i < 4) ? (ty * 4 + i) : (64 + ty * 4 + (i - 4));
            int mi = m0 + mloc;
            if (mi >= count) continue;
            int tok = toks[mloc];
            float g = gts[mloc];
            float* orow = out + (size_t)tok * DIM + n0;
            #pragma unroll
            for (int jj = 0; jj < 4; jj++) {
                int nloc = (jj < 2) ? (tx * 4 + jj * 2) : (64 + tx * 4 + (jj - 2) * 2);
                float2 v = *(float2*)&acc[i][jj];
                atomicAdd(orow + nloc,     g * (v.x + b2[e * DIM + n0 + nloc]));
                atomicAdd(orow + nloc + 1, g * (v.y + b2[e * DIM + n0 + nloc + 1]));
            }
        }
    }
#endif
}

// ==================== launch ====================
extern "C" void kernel_launch(void* const* d_in, const int* in_sizes, int n_in,
                              void* d_out, int out_size) {
    const float* x       = (const float*)d_in[0];
    const float* anchors = (const float*)d_in[1];
    const float* W1      = (const float*)d_in[2];
    const float* b1      = (const float*)d_in[3];
    const float* W2      = (const float*)d_in[4];
    const float* b2      = (const float*)d_in[5];
    float* out = (float*)d_out;

    static int attr_done = 0;
    if (!attr_done) {
        cudaFuncSetAttribute(k_gemm1, cudaFuncAttributeMaxDynamicSharedMemorySize, SMEM_DYN);
        cudaFuncSetAttribute(k_gemm2, cudaFuncAttributeMaxDynamicSharedMemorySize, SMEM_DYN);
        attr_done = 1;
    }

    const int OUT_END = T_TOK * DIM;
    const int AN_END  = OUT_END + NEXP * DIM;
    const int SC_END  = AN_END + T_TOK * NEXP;
    const int IX_END  = SC_END + T_TOK * 2;
    int write_an = (out_size >= AN_END) ? 1 : 0;
    int wflags = ((out_size >= SC_END) ? 1 : 0) | ((out_size >= IX_END) ? 2 : 0);

    k_anchors<<<1, 256>>>(anchors, out + OUT_END, write_an);
    k_route<<<512, 256>>>(x, out, out + AN_END, out + SC_END, wflags);
    dim3 gx(T_TOK / TM, NEXP);
    k_xpose<<<gx, 128>>>();
    dim3 g1(FDIM / TN, T_TOK / TM, NEXP);
    k_gemm1<<<g1, NTHREADS, SMEM_DYN>>>(x, W1, b1);
    dim3 g2(DIM / TN, T_TOK / TM, NEXP);
    k_gemm2<<<g2, NTHREADS, SMEM_DYN>>>(W2, b2, out);
}

// round 12
// speedup vs baseline: 1.0954x; 1.0954x over previous
#include <cuda_runtime.h>
#include <cstdint>

#define T_TOK 4096
#define DIM   512
#define FDIM  2048
#define NEXP  8
#define EPSV  1e-8f

#define TM   128
#define TN   128
#define KC   32
#define NSTG 4
#define NGRP (NEXP * (T_TOK / TM))
#define XT_STRIDE ((DIM / KC) * 16 * 128)
#define HT_STRIDE ((FDIM / KC) * 16 * 128)

#if defined(__CUDA_ARCH__) && defined(__CUDA_ARCH_FEAT_SM103_ALL)
#define USE_TC 1
#else
#define USE_TC 0
#endif

#define SMEM_STAGE 16384            // B hi 8KB + B lo 8KB (128 rows x 32 bf16, SW64)
#define SMEM_DYN   (NSTG * SMEM_STAGE + 1024)
#define NTHREADS   288

// -------- scratch --------
__device__ float    g_anchors_n[NEXP * DIM];
__device__ int      g_cnt[NEXP];
__device__ int      g_tok[NEXP][T_TOK];
__device__ float    g_gate[NEXP][T_TOK];
__device__ uint32_t g_Xhi[T_TOK * (DIM / 2)];
__device__ uint32_t g_Xlo[T_TOK * (DIM / 2)];
__device__ uint32_t g_XThi[NGRP * XT_STRIDE];
__device__ uint32_t g_XTlo[NGRP * XT_STRIDE];
__device__ uint32_t g_HThi[(size_t)NGRP * HT_STRIDE];
__device__ uint32_t g_HTlo[(size_t)NGRP * HT_STRIDE];
__device__ float    g_H[(2 * T_TOK) * FDIM];   // fallback only

// ==================== helpers ====================
__device__ __forceinline__ float gelu_f(float h) {
    return 0.5f * h * (1.f + erff(h * 0.7071067811865476f));
}
__device__ __forceinline__ void split2_bf16(float v0, float v1, uint32_t& hw, uint32_t& lw) {
    asm("cvt.rn.satfinite.bf16x2.f32 %0, %1, %2;" : "=r"(hw) : "f"(v1), "f"(v0));
    float h0 = __uint_as_float(hw << 16);
    float h1 = __uint_as_float(hw & 0xffff0000u);
    asm("cvt.rn.satfinite.bf16x2.f32 %0, %1, %2;" : "=r"(lw) : "f"(v1 - h1), "f"(v0 - h0));
}
__device__ __forceinline__ unsigned long long pack2(float a) {
    unsigned long long r;
    asm("mov.b64 %0, {%1, %1};" : "=l"(r) : "f"(a));
    return r;
}
__device__ __forceinline__ unsigned long long fma2(unsigned long long a,
                                                   unsigned long long b,
                                                   unsigned long long c) {
    unsigned long long d;
    asm("fma.rn.f32x2 %0, %1, %2, %3;" : "=l"(d) : "l"(a), "l"(b), "l"(c));
    return d;
}
__device__ __forceinline__ void ld16(uint32_t* dst, const uint32_t* src) {
    #pragma unroll
    for (int i = 0; i < 4; i++) {
        uint4 v = ((const uint4*)src)[i];
        dst[4 * i + 0] = v.x; dst[4 * i + 1] = v.y;
        dst[4 * i + 2] = v.z; dst[4 * i + 3] = v.w;
    }
}

#if USE_TC
__device__ __forceinline__ uint32_t sm2u32(const void* p) {
    uint32_t a;
    asm("{ .reg .u64 t; cvta.to.shared.u64 t, %1; cvt.u32.u64 %0, t; }" : "=r"(a) : "l"(p));
    return a;
}
__device__ __forceinline__ bool elect1() {
    uint32_t r;
    asm volatile("{ .reg .pred p; elect.sync _|p, 0xFFFFFFFF; selp.b32 %0, 1, 0, p; }" : "=r"(r));
    return r != 0;
}
__device__ __forceinline__ void sts128u(uint32_t a, const uint32_t* w) {
    asm volatile("st.shared.v4.b32 [%0], {%1,%2,%3,%4};"
                 :: "r"(a), "r"(w[0]), "r"(w[1]), "r"(w[2]), "r"(w[3]) : "memory");
}
__device__ __forceinline__ void mbar_init(uint32_t a, uint32_t c) {
    asm volatile("mbarrier.init.shared.b64 [%0], %1;" :: "r"(a), "r"(c) : "memory");
}
__device__ __forceinline__ void mbar_inval(uint32_t a) {
    asm volatile("mbarrier.inval.shared.b64 [%0];" :: "r"(a) : "memory");
}
__device__ __forceinline__ void mbar_arrive(uint32_t a) {
    asm volatile("mbarrier.arrive.shared.b64 _, [%0];" :: "r"(a) : "memory");
}
__device__ __forceinline__ void mbar_wait(uint32_t a, uint32_t ph) {
    uint32_t done;
    asm volatile("{\n\t.reg .pred p;\n\t"
                 "mbarrier.try_wait.parity.acquire.cta.shared::cta.b64 p, [%1], %2;\n\t"
                 "selp.b32 %0, 1, 0, p;\n\t}"
                 : "=r"(done) : "r"(a), "r"(ph) : "memory");
    if (!done) {
        asm volatile("{\n\t.reg .pred P1;\n\t"
                     "LW%=:\n\t"
                     "mbarrier.try_wait.parity.acquire.cta.shared::cta.b64 P1, [%0], %1, 0x989680;\n\t"
                     "@P1 bra.uni LD%=;\n\t"
                     "bra.uni LW%=;\n\t"
                     "LD%=:\n\t}"
                     :: "r"(a), "r"(ph) : "memory");
    }
}
__device__ __forceinline__ void tc_commit(uint32_t mb) {
    asm volatile("tcgen05.commit.cta_group::1.mbarrier::arrive::one.shared::cluster.b64 [%0];"
                 :: "r"(mb) : "memory");
}
__device__ __forceinline__ void mma_f16_ts(uint32_t d, uint32_t a, uint64_t b,
                                           uint32_t idesc, uint32_t en) {
    asm volatile("{\n\t.reg .pred p;\n\tsetp.ne.u32 p, %4, 0;\n\t"
                 "tcgen05.mma.cta_group::1.kind::f16 [%0], [%1], %2, %3, {%5,%5,%5,%5}, p;\n\t}"
                 :: "r"(d), "r"(a), "l"(b), "r"(idesc), "r"(en), "r"(0u) : "memory");
}
#define STTM16U(ta, r) \
    asm volatile( \
        "tcgen05.st.sync.aligned.32x32b.x16.b32 [%0], " \
        "{%1, %2, %3, %4, %5, %6, %7, %8, " \
        " %9, %10, %11, %12, %13, %14, %15, %16};" \
        :: "r"(ta), \
           "r"((r)[0]),  "r"((r)[1]),  "r"((r)[2]),  "r"((r)[3]), \
           "r"((r)[4]),  "r"((r)[5]),  "r"((r)[6]),  "r"((r)[7]), \
           "r"((r)[8]),  "r"((r)[9]),  "r"((r)[10]), "r"((r)[11]), \
           "r"((r)[12]), "r"((r)[13]), "r"((r)[14]), "r"((r)[15]) \
        : "memory")
#define LDTM32(r, ta) \
    asm volatile( \
        "tcgen05.ld.sync.aligned.32x32b.x32.b32 " \
        "{%0, %1, %2, %3, %4, %5, %6, %7, " \
        " %8, %9, %10, %11, %12, %13, %14, %15, " \
        " %16, %17, %18, %19, %20, %21, %22, %23, " \
        " %24, %25, %26, %27, %28, %29, %30, %31}, [%32];" \
        : "=r"((r)[0]),  "=r"((r)[1]),  "=r"((r)[2]),  "=r"((r)[3]), \
          "=r"((r)[4]),  "=r"((r)[5]),  "=r"((r)[6]),  "=r"((r)[7]), \
          "=r"((r)[8]),  "=r"((r)[9]),  "=r"((r)[10]), "=r"((r)[11]), \
          "=r"((r)[12]), "=r"((r)[13]), "=r"((r)[14]), "=r"((r)[15]), \
          "=r"((r)[16]), "=r"((r)[17]), "=r"((r)[18]), "=r"((r)[19]), \
          "=r"((r)[20]), "=r"((r)[21]), "=r"((r)[22]), "=r"((r)[23]), \
          "=r"((r)[24]), "=r"((r)[25]), "=r"((r)[26]), "=r"((r)[27]), \
          "=r"((r)[28]), "=r"((r)[29]), "=r"((r)[30]), "=r"((r)[31]) \
        : "r"(ta))

__device__ __forceinline__ uint64_t mk_desc64(uint32_t addr) {
    return ((uint64_t)4 << 61) | ((uint64_t)1 << 46) | ((uint64_t)32 << 32) |
           ((uint64_t)1 << 16) | ((uint64_t)(addr >> 4) & 0x3FFF);
}
__device__ __forceinline__ uint32_t swoff64(int r, int c16) {
    return (uint32_t)(((r >> 3) << 9) + ((r & 7) << 6) + (((c16 ^ ((r >> 1) & 3)) & 3) << 4));
}
#define IDESC_BF ((1u << 4) | (1u << 7) | (1u << 10) | ((TN / 8) << 17) | ((TM / 16) << 24))
#define TMEM_NCOLS 256
#define TM_D 0
#define TM_A(st) (128 + (st) * 32)

// ---- producer macros; A reads transposed planes (coalesced LDG.32) ----
#define A_LOAD(B, cc) do { \
    _Pragma("unroll") \
    for (int j_ = 0; j_ < 16; j_++) { \
        Ah##B[j_] = rhi[(size_t)(cc) * 2048 + j_ * 128]; \
        Al##B[j_] = rlo[(size_t)(cc) * 2048 + j_ * 128]; \
    } \
} while (0)
#define A_STEP(B, cc) do { \
    const int st_ = (cc) & (NSTG - 1); \
    if ((cc) >= NSTG) { \
        if (lane == 0) mbar_wait(mb_done + st_ * 8, (((cc) >> 2) + 1) & 1); \
        __syncwarp(); \
        asm volatile("tcgen05.fence::after_thread_sync;" ::: "memory"); \
    } \
    STTM16U(tmem + TM_A(st_) + woff, Ah##B); \
    STTM16U(tmem + TM_A(st_) + 16 + woff, Al##B); \
    asm volatile("tcgen05.wait::st.sync.aligned;" ::: "memory"); \
    asm volatile("tcgen05.fence::before_thread_sync;" ::: "memory"); \
    if (lane == 0) mbar_arrive(mb_full + st_ * 8); \
} while (0)

#define B_LOAD(B, cc) do { \
    _Pragma("unroll") \
    for (int k_ = 0; k_ < KC; k_++) fb##B[k_] = wp[(size_t)((cc) * KC + k_) * wld]; \
} while (0)
#define B_STEP(B, cc) do { \
    const int st_ = (cc) & (NSTG - 1); \
    if ((cc) >= NSTG) { \
        if (lane == 0) mbar_wait(mb_done + st_ * 8, (((cc) >> 2) + 1) & 1); \
        __syncwarp(); \
    } \
    uint32_t hw_[16], lw_[16]; \
    _Pragma("unroll") \
    for (int i_ = 0; i_ < 16; i_++) \
        split2_bf16(fb##B[2 * i_], fb##B[2 * i_ + 1], hw_[i_], lw_[i_]); \
    const uint32_t Bhi_ = sm + st_ * SMEM_STAGE; \
    const uint32_t Blo_ = Bhi_ + 8192; \
    _Pragma("unroll") \
    for (int j_ = 0; j_ < 4; j_++) { \
        sts128u(Bhi_ + swoff64(n, j_), hw_ + 4 * j_); \
        sts128u(Blo_ + swoff64(n, j_), lw_ + 4 * j_); \
    } \
    asm volatile("fence.proxy.async.shared::cta;" ::: "memory"); \
    __syncwarp(); \
    if (lane == 0) mbar_arrive(mb_full + st_ * 8); \
} while (0)
#endif  // USE_TC

// ==================== small kernels ====================
__global__ void k_anchors(const float* __restrict__ A, float* __restrict__ an_out,
                          int write_an) {
    int w = threadIdx.x >> 5, lane = threadIdx.x & 31;
    if (threadIdx.x < NEXP) g_cnt[threadIdx.x] = 0;
    float ss = 0.f;
    for (int d = lane; d < DIM; d += 32) { float v = A[w * DIM + d]; ss += v * v; }
    #pragma unroll
    for (int o = 16; o; o >>= 1) ss += __shfl_xor_sync(0xffffffffu, ss, o);
    float inv = 1.f / fmaxf(sqrtf(ss), EPSV);
    for (int d = lane; d < DIM; d += 32) {
        float v = A[w * DIM + d] * inv;
        g_anchors_n[w * DIM + d] = v;
        if (write_an) an_out[w * DIM + d] = v;
    }
}

__global__ void k_route(const float* __restrict__ x, float* __restrict__ out,
                        float* __restrict__ scores_out,
                        float* __restrict__ idx_out, int wflags) {
    {
        int t = blockIdx.x * blockDim.x + threadIdx.x;
        float4* o4 = (float4*)out;
        #pragma unroll
        for (int j = 0; j < 4; j++)
            o4[t * 4 + j] = make_float4(0.f, 0.f, 0.f, 0.f);
    }
    int wid = (blockIdx.x * blockDim.x + threadIdx.x) >> 5;
    int lane = threadIdx.x & 31;
    if (wid >= T_TOK) return;
    const float* xr = x + (size_t)wid * DIM;
    float xx = 0.f;
    float dt[NEXP];
    #pragma unroll
    for (int e = 0; e < NEXP; e++) dt[e] = 0.f;
    #pragma unroll
    for (int j = 0; j < 8; j++) {
        int d0 = lane * 2 + j * 64;
        float v0 = xr[d0], v1 = xr[d0 + 1];
        xx += v0 * v0 + v1 * v1;
        #pragma unroll
        for (int e = 0; e < NEXP; e++)
            dt[e] += v0 * g_anchors_n[e * DIM + d0] + v1 * g_anchors_n[e * DIM + d0 + 1];
        uint32_t hw, lw;
        split2_bf16(v0, v1, hw, lw);
        g_Xhi[(size_t)wid * (DIM / 2) + lane + j * 32] = hw;
        g_Xlo[(size_t)wid * (DIM / 2) + lane + j * 32] = lw;
    }
    #pragma unroll
    for (int o = 16; o; o >>= 1) {
        xx += __shfl_xor_sync(0xffffffffu, xx, o);
        #pragma unroll
        for (int e = 0; e < NEXP; e++) dt[e] += __shfl_xor_sync(0xffffffffu, dt[e], o);
    }
    if (lane == 0) {
        float inv = 1.f / fmaxf(sqrtf(xx), EPSV);
        float s[NEXP];
        #pragma unroll
        for (int e = 0; e < NEXP; e++) s[e] = dt[e] * inv;
        int i1 = 0; float v1 = s[0];
        #pragma unroll
        for (int e = 1; e < NEXP; e++) if (s[e] > v1) { v1 = s[e]; i1 = e; }
        int i2 = -1; float v2 = -1e30f;
        #pragma unroll
        for (int e = 0; e < NEXP; e++) if (e != i1 && s[e] > v2) { v2 = s[e]; i2 = e; }
        float e2 = expf(v2 - v1);
        float denom = 1.f / (1.f + e2);
        float g1 = denom, g2 = e2 * denom;
        int s1 = atomicAdd(&g_cnt[i1], 1);
        g_tok[i1][s1] = wid; g_gate[i1][s1] = g1;
        int s2 = atomicAdd(&g_cnt[i2], 1);
        g_tok[i2][s2] = wid; g_gate[i2][s2] = g2;
        if (wflags & 1) {
            #pragma unroll
            for (int e = 0; e < NEXP; e++) scores_out[wid * NEXP + e] = s[e];
        }
        if (wflags & 2) {
            idx_out[wid * 2 + 0] = (float)i1;
            idx_out[wid * 2 + 1] = (float)i2;
        }
    }
}

__global__ void k_xpose() {
    const int e = blockIdx.y, mt = blockIdx.x;
    const int count = g_cnt[e];
    const int m0 = mt * TM;
    if (m0 >= count) return;
    const int gid = e * (T_TOK / TM) + mt;
    const int tid = threadIdx.x;
    const int tok = g_tok[e][min(m0 + tid, count - 1)];
    const uint32_t* rhi = g_Xhi + (size_t)tok * (DIM / 2);
    const uint32_t* rlo = g_Xlo + (size_t)tok * (DIM / 2);
    uint32_t* dhi = g_XThi + (size_t)gid * XT_STRIDE;
    uint32_t* dlo = g_XTlo + (size_t)gid * XT_STRIDE;
    for (int c = 0; c < DIM / KC; c++) {
        uint32_t h[16], l[16];
        ld16(h, rhi + c * 16);
        ld16(l, rlo + c * 16);
        #pragma unroll
        for (int j = 0; j < 16; j++) {
            dhi[c * 2048 + j * 128 + tid] = h[j];
            dlo[c * 2048 + j * 128 + tid] = l[j];
        }
    }
}

// ==================== GEMM1 ====================
__global__ __launch_bounds__(NTHREADS, 2)
void k_gemm1(const float* __restrict__ x, const float* __restrict__ W1,
             const float* __restrict__ b1) {
    const int e = blockIdx.z;
    const int count = g_cnt[e];
    const int m0 = blockIdx.y * TM;
    if (m0 >= count) return;
    const int n0 = blockIdx.x * TN;
    const int gid = e * (T_TOK / TM) + blockIdx.y;
    const int tid = threadIdx.x;
    const int wid = tid >> 5, lane = tid & 31;
    extern __shared__ char dynraw[];
    __shared__ int toks[TM];
    if (tid < TM) toks[tid] = g_tok[e][min(m0 + tid, count - 1)];

#if USE_TC
    __shared__ __align__(8) unsigned long long s_bar[2 * NSTG];
    __shared__ uint32_t s_tmem;
    const uint32_t sm = (sm2u32(dynraw) + 1023u) & ~1023u;
    if (tid == 0) {
        for (int s = 0; s < NSTG; s++) {
            mbar_init(sm2u32(&s_bar[s]), 1);
            mbar_init(sm2u32(&s_bar[NSTG + s]), 8);
        }
    }
    if (wid == 0) {
        asm volatile("tcgen05.alloc.cta_group::1.sync.aligned.shared::cta.b32 [%0], %1;"
                     :: "r"(sm2u32(&s_tmem)), "r"((uint32_t)TMEM_NCOLS) : "memory");
        asm volatile("tcgen05.relinquish_alloc_permit.cta_group::1.sync.aligned;");
    }
    __syncthreads();
    const uint32_t tmem = s_tmem;
    const uint32_t mb_done = sm2u32(&s_bar[0]);
    const uint32_t mb_full = sm2u32(&s_bar[NSTG]);
    const int NC = DIM / KC;   // 16

    if (wid < 4) {
        const uint32_t* rhi = g_XThi + (size_t)gid * XT_STRIDE + tid;
        const uint32_t* rlo = g_XTlo + (size_t)gid * XT_STRIDE + tid;
        const uint32_t woff = ((uint32_t)wid) << 21;
        uint32_t Ah0[16], Al0[16], Ah1[16], Al1[16];
        A_LOAD(0, 0);
        for (int c = 0; c < NC; c += 2) {
            A_LOAD(1, c + 1);
            A_STEP(0, c);
            if (c + 2 < NC) A_LOAD(0, c + 2);
            A_STEP(1, c + 1);
        }
    } else if (wid < 8) {
        const int n = tid - 128;
        const float* wp = W1 + (size_t)e * DIM * FDIM + n0 + n;
        const int wld = FDIM;
        float fb0[KC], fb1[KC];
        B_LOAD(0, 0);
        for (int c = 0; c < NC; c += 2) {
            B_LOAD(1, c + 1);
            B_STEP(0, c);
            if (c + 2 < NC) B_LOAD(0, c + 2);
            B_STEP(1, c + 1);
        }
    } else {
        if (elect1()) {
            for (int c = 0; c < NC; c++) {
                const int st = c & (NSTG - 1);
                mbar_wait(mb_full + st * 8, (c >> 2) & 1);
                asm volatile("tcgen05.fence::after_thread_sync;" ::: "memory");
                const uint32_t Bhi = sm + st * SMEM_STAGE;
                uint64_t dh = mk_desc64(Bhi), dl = mk_desc64(Bhi + 8192);
                const uint32_t ah = tmem + TM_A(st), al = ah + 16;
                #pragma unroll
                for (int s2 = 0; s2 < 2; s2++) {
                    mma_f16_ts(tmem + TM_D, ah + s2 * 8, dh + s2 * 2, IDESC_BF,
                               (c | s2) ? 1u : 0u);
                    mma_f16_ts(tmem + TM_D, ah + s2 * 8, dl + s2 * 2, IDESC_BF, 1u);
                    mma_f16_ts(tmem + TM_D, al + s2 * 8, dh + s2 * 2, IDESC_BF, 1u);
                }
                tc_commit(mb_done + st * 8);
            }
        }
    }
    __syncthreads();
    mbar_wait(mb_done + ((NC - 1) & (NSTG - 1)) * 8, ((NC - 1) >> 2) & 1);
    asm volatile("tcgen05.fence::after_thread_sync;" ::: "memory");

    if (wid < 8) {
        const int sp = wid & 3, half = wid >> 2;
        const int ml = sp * 32 + lane;
        const int mi = m0 + ml;
        const bool valid = mi < count;
        uint32_t* dhi = g_HThi + (size_t)gid * HT_STRIDE;
        uint32_t* dlo = g_HTlo + (size_t)gid * HT_STRIDE;
        const float* bp = b1 + (size_t)e * FDIM + n0;
        #pragma unroll
        for (int cb = 0; cb < 2; cb++) {
            const uint32_t c0 = half * 64 + cb * 32;
            uint32_t rg[32];
            LDTM32(rg, tmem + TM_D + c0);
            asm volatile("tcgen05.wait::ld.sync.aligned;" ::: "memory");
            if (valid) {
                const int chunk = (n0 + (int)c0) >> 5;
                #pragma unroll
                for (int i = 0; i < 16; i++) {
                    float y0 = gelu_f(__uint_as_float(rg[2 * i + 0]) + bp[c0 + 2 * i + 0]);
                    float y1 = gelu_f(__uint_as_float(rg[2 * i + 1]) + bp[c0 + 2 * i + 1]);
                    uint32_t hw, lw;
                    split2_bf16(y0, y1, hw, lw);
                    dhi[(size_t)chunk * 2048 + i * 128 + ml] = hw;
                    dlo[(size_t)chunk * 2048 + i * 128 + ml] = lw;
                }
            }
        }
        asm volatile("tcgen05.fence::before_thread_sync;" ::: "memory");
    }
    __syncthreads();
    if (tid == 0)
        for (int s = 0; s < 2 * NSTG; s++) mbar_inval(sm2u32(&s_bar[s]));
    if (wid == 0) {
        asm volatile("tcgen05.dealloc.cta_group::1.sync.aligned.b32 %0, %1;"
                     :: "r"(tmem), "r"((uint32_t)TMEM_NCOLS));
    }
#else
    // ---------- FFMA f32x2 fallback (tid<256 active) ----------
    __shared__ int s_base;
    if (tid == 0) {
        int b = 0;
        for (int i = 0; i < e; i++) b += g_cnt[i];
        s_base = b;
    }
    float* As = (float*)dynraw;
    float* Bs = As + 16 * 132;
    __syncthreads();
    const int base = s_base;
    const int tx = tid & 15, ty = tid >> 4;
    unsigned long long acc[8][4];
    #pragma unroll
    for (int i = 0; i < 8; i++)
        #pragma unroll
        for (int j = 0; j < 4; j++) acc[i][j] = 0ull;
    const float* Wb = W1 + (size_t)e * DIM * FDIM + n0;
    for (int k0 = 0; k0 < DIM; k0 += 16) {
        if (tid < 256) {
            #pragma unroll
            for (int j = 0; j < 2; j++) {
                int q = tid + j * 256;
                int m = q >> 2, kq = q & 3;
                float4 v = *(const float4*)(x + (size_t)toks[m] * DIM + k0 + kq * 4);
                As[(kq * 4 + 0) * 132 + m] = v.x; As[(kq * 4 + 1) * 132 + m] = v.y;
                As[(kq * 4 + 2) * 132 + m] = v.z; As[(kq * 4 + 3) * 132 + m] = v.w;
            }
            #pragma unroll
            for (int j = 0; j < 2; j++) {
                int q = tid + j * 256;
                int kk = q >> 5, nq = q & 31;
                float4 v = *(const float4*)(Wb + (size_t)(k0 + kk) * FDIM + nq * 4);
                *(float4*)&Bs[kk * 132 + nq * 4] = v;
            }
        }
        __syncthreads();
        if (tid < 256) {
            #pragma unroll
            for (int k = 0; k < 16; k++) {
                float4 a0 = *(float4*)&As[k * 132 + ty * 4];
                float4 a1 = *(float4*)&As[k * 132 + 64 + ty * 4];
                float4 b0 = *(float4*)&Bs[k * 132 + tx * 4];
                float4 b1r = *(float4*)&Bs[k * 132 + 64 + tx * 4];
                unsigned long long bb[4];
                bb[0] = ((const unsigned long long*)&b0)[0];
                bb[1] = ((const unsigned long long*)&b0)[1];
                bb[2] = ((const unsigned long long*)&b1r)[0];
                bb[3] = ((const unsigned long long*)&b1r)[1];
                float av[8] = {a0.x, a0.y, a0.z, a0.w, a1.x, a1.y, a1.z, a1.w};
                #pragma unroll
                for (int i = 0; i < 8; i++) {
                    unsigned long long aa = pack2(av[i]);
                    #pragma unroll
                    for (int jj = 0; jj < 4; jj++) acc[i][jj] = fma2(aa, bb[jj], acc[i][jj]);
                }
            }
        }
        __syncthreads();
    }
    if (tid < 256) {
        #pragma unroll
        for (int i = 0; i < 8; i++) {
            int mloc = (i < 4) ? (ty * 4 + i) : (64 + ty * 4 + (i - 4));
            int mi = m0 + mloc;
            if (mi >= count) continue;
            float* Hrow = g_H + (size_t)(base + mi) * FDIM + n0;
            #pragma unroll
            for (int jj = 0; jj < 4; jj++) {
                int nloc = (jj < 2) ? (tx * 4 + jj * 2) : (64 + tx * 4 + (jj - 2) * 2);
                float2 v = *(float2*)&acc[i][jj];
                float h0 = gelu_f(v.x + b1[e * FDIM + n0 + nloc]);
                float h1 = gelu_f(v.y + b1[e * FDIM + n0 + nloc + 1]);
                *(float2*)(Hrow + nloc) = make_float2(h0, h1);
            }
        }
    }
#endif
}

// ==================== GEMM2 (K-split 2): out += gate*(H @ W2[e] + b2[e]) ====================
__global__ __launch_bounds__(NTHREADS, 2)
void k_gemm2(const float* __restrict__ W2, const float* __restrict__ b2,
             float* __restrict__ out) {
    const int e = blockIdx.z;
    const int count = g_cnt[e];
    const int m0 = blockIdx.y * TM;
    if (m0 >= count) return;
    const int n0 = (blockIdx.x >> 1) * TN;
    const int ks = blockIdx.x & 1;
    const int gid = e * (T_TOK / TM) + blockIdx.y;
    const int tid = threadIdx.x;
    const int wid = tid >> 5, lane = tid & 31;
    extern __shared__ char dynraw[];
    __shared__ int   toks[TM];
    __shared__ float gts[TM];
    if (tid < TM) {
        int mi = min(m0 + tid, count - 1);
        toks[tid] = g_tok[e][mi];
        gts[tid]  = g_gate[e][mi];
    }

#if USE_TC
    __shared__ __align__(8) unsigned long long s_bar[2 * NSTG];
    __shared__ uint32_t s_tmem;
    const uint32_t sm = (sm2u32(dynraw) + 1023u) & ~1023u;
    if (tid == 0) {
        for (int s = 0; s < NSTG; s++) {
            mbar_init(sm2u32(&s_bar[s]), 1);
            mbar_init(sm2u32(&s_bar[NSTG + s]), 8);
        }
    }
    if (wid == 0) {
        asm volatile("tcgen05.alloc.cta_group::1.sync.aligned.shared::cta.b32 [%0], %1;"
                     :: "r"(sm2u32(&s_tmem)), "r"((uint32_t)TMEM_NCOLS) : "memory");
        asm volatile("tcgen05.relinquish_alloc_permit.cta_group::1.sync.aligned;");
    }
    __syncthreads();
    const uint32_t tmem = s_tmem;
    const uint32_t mb_done = sm2u32(&s_bar[0]);
    const uint32_t mb_full = sm2u32(&s_bar[NSTG]);
    const int NC = (FDIM / 2) / KC;   // 32 chunks per split
    const size_t kcoff = (size_t)ks * NC * 2048;       // word offset into HT planes
    const int keoff = ks * (FDIM / 2);                 // k-row offset into W2

    if (wid < 4) {
        const uint32_t* rhi = g_HThi + (size_t)gid * HT_STRIDE + kcoff + tid;
        const uint32_t* rlo = g_HTlo + (size_t)gid * HT_STRIDE + kcoff + tid;
        const uint32_t woff = ((uint32_t)wid) << 21;
        uint32_t Ah0[16], Al0[16], Ah1[16], Al1[16];
        A_LOAD(0, 0);
        for (int c = 0; c < NC; c += 2) {
            A_LOAD(1, c + 1);
            A_STEP(0, c);
            if (c + 2 < NC) A_LOAD(0, c + 2);
            A_STEP(1, c + 1);
        }
    } else if (wid < 8) {
        const int n = tid - 128;
        const float* wp = W2 + (size_t)e * FDIM * DIM + (size_t)keoff * DIM + n0 + n;
        const int wld = DIM;
        float fb0[KC], fb1[KC];
        B_LOAD(0, 0);
        for (int c = 0; c < NC; c += 2) {
            B_LOAD(1, c + 1);
            B_STEP(0, c);
            if (c + 2 < NC) B_LOAD(0, c + 2);
            B_STEP(1, c + 1);
        }
    } else {
        if (elect1()) {
            for (int c = 0; c < NC; c++) {
                const int st = c & (NSTG - 1);
                mbar_wait(mb_full + st * 8, (c >> 2) & 1);
                asm volatile("tcgen05.fence::after_thread_sync;" ::: "memory");
                const uint32_t Bhi = sm + st * SMEM_STAGE;
                uint64_t dh = mk_desc64(Bhi), dl = mk_desc64(Bhi + 8192);
                const uint32_t ah = tmem + TM_A(st), al = ah + 16;
                #pragma unroll
                for (int s2 = 0; s2 < 2; s2++) {
                    mma_f16_ts(tmem + TM_D, ah + s2 * 8, dh + s2 * 2, IDESC_BF,
                               (c | s2) ? 1u : 0u);
                    mma_f16_ts(tmem + TM_D, ah + s2 * 8, dl + s2 * 2, IDESC_BF, 1u);
                    mma_f16_ts(tmem + TM_D, al + s2 * 8, dh + s2 * 2, IDESC_BF, 1u);
                }
                tc_commit(mb_done + st * 8);
            }
        }
    }
    __syncthreads();
    mbar_wait(mb_done + ((NC - 1) & (NSTG - 1)) * 8, ((NC - 1) >> 2) & 1);
    asm volatile("tcgen05.fence::after_thread_sync;" ::: "memory");

    if (wid < 8) {
        const int sp = wid & 3, half = wid >> 2;
        const int ml = sp * 32 + lane;
        const int mi = m0 + ml;
        const bool valid = mi < count;
        const int tok = toks[ml];
        const float gate = gts[ml];
        float* orow = out + (size_t)tok * DIM + n0;
        const float* bp = b2 + (size_t)e * DIM + n0;
        #pragma unroll
        for (int cb = 0; cb < 2; cb++) {
            const uint32_t c0 = half * 64 + cb * 32;
            uint32_t rg[32];
            LDTM32(rg, tmem + TM_D + c0);
            asm volatile("tcgen05.wait::ld.sync.aligned;" ::: "memory");
            if (valid) {
                #pragma unroll
                for (int i = 0; i < 32; i++) {
                    float y = __uint_as_float(rg[i]) + (ks == 0 ? bp[c0 + i] : 0.f);
                    atomicAdd(orow + c0 + i, gate * y);
                }
            }
        }
        asm volatile("tcgen05.fence::before_thread_sync;" ::: "memory");
    }
    __syncthreads();
    if (tid == 0)
        for (int s = 0; s < 2 * NSTG; s++) mbar_inval(sm2u32(&s_bar[s]));
    if (wid == 0) {
        asm volatile("tcgen05.dealloc.cta_group::1.sync.aligned.b32 %0, %1;"
                     :: "r"(tmem), "r"((uint32_t)TMEM_NCOLS));
    }
#else
    // ---------- FFMA f32x2 fallback (tid<256 active) ----------
    __shared__ int s_base;
    if (tid == 0) {
        int b = 0;
        for (int i = 0; i < e; i++) b += g_cnt[i];
        s_base = b;
    }
    float* As = (float*)dynraw;
    float* Bs = As + 16 * 132;
    __syncthreads();
    const int base = s_base;
    const int tx = tid & 15, ty = tid >> 4;
    unsigned long long acc[8][4];
    #pragma unroll
    for (int i = 0; i < 8; i++)
        #pragma unroll
        for (int j = 0; j < 4; j++) acc[i][j] = 0ull;
    const float* Wb = W2 + (size_t)e * FDIM * DIM + (size_t)(ks * (FDIM / 2)) * DIM + n0;
    const int kbase = ks * (FDIM / 2);
    for (int k0 = 0; k0 < FDIM / 2; k0 += 16) {
        if (tid < 256) {
            #pragma unroll
            for (int j = 0; j < 2; j++) {
                int q = tid + j * 256;
                int m = q >> 2, kq = q & 3;
                int rowg = base + min(m0 + m, count - 1);
                float4 v = *(const float4*)(g_H + (size_t)rowg * FDIM + kbase + k0 + kq * 4);
                As[(kq * 4 + 0) * 132 + m] = v.x; As[(kq * 4 + 1) * 132 + m] = v.y;
                As[(kq * 4 + 2) * 132 + m] = v.z; As[(kq * 4 + 3) * 132 + m] = v.w;
            }
            #pragma unroll
            for (int j = 0; j < 2; j++) {
                int q = tid + j * 256;
                int kk = q >> 5, nq = q & 31;
                float4 v = *(const float4*)(Wb + (size_t)(k0 + kk) * DIM + nq * 4);
                *(float4*)&Bs[kk * 132 + nq * 4] = v;
            }
        }
        __syncthreads();
        if (tid < 256) {
            #pragma unroll
            for (int k = 0; k < 16; k++) {
                float4 a0 = *(float4*)&As[k * 132 + ty * 4];
                float4 a1 = *(float4*)&As[k * 132 + 64 + ty * 4];
                float4 b0 = *(float4*)&Bs[k * 132 + tx * 4];
                float4 b1r = *(float4*)&Bs[k * 132 + 64 + tx * 4];
                unsigned long long bb[4];
                bb[0] = ((const unsigned long long*)&b0)[0];
                bb[1] = ((const unsigned long long*)&b0)[1];
                bb[2] = ((const unsigned long long*)&b1r)[0];
                bb[3] = ((const unsigned long long*)&b1r)[1];
                float av[8] = {a0.x, a0.y, a0.z, a0.w, a1.x, a1.y, a1.z, a1.w};
                #pragma unroll
                for (int i = 0; i < 8; i++) {
                    unsigned long long aa = pack2(av[i]);
                    #pragma unroll
                    for (int jj = 0; jj < 4; jj++) acc[i][jj] = fma2(aa, bb[jj], acc[i][jj]);
                }
            }
        }
        __syncthreads();
    }
    if (tid < 256) {
        #pragma unroll
        for (int i = 0; i < 8; i++) {
            int mloc = (i < 4) ? (ty * 4 + i) : (64 + ty * 4 + (i - 4));
            int mi = m0 + mloc;
            if (mi >= count) continue;
            int tok = toks[mloc];
            float g = gts[mloc];
            float* orow = out + (size_t)tok * DIM + n0;
            #pragma unroll
            for (int jj = 0; jj < 4; jj++) {
                int nloc = (jj < 2) ? (tx * 4 + jj * 2) : (64 + tx * 4 + (jj - 2) * 2);
                float2 v = *(float2*)&acc[i][jj];
                float bv0 = (ks == 0) ? b2[e * DIM + n0 + nloc] : 0.f;
                float bv1 = (ks == 0) ? b2[e * DIM + n0 + nloc + 1] : 0.f;
                atomicAdd(orow + nloc,     g * (v.x + bv0));
                atomicAdd(orow + nloc + 1, g * (v.y + bv1));
            }
        }
    }
#endif
}

// ==================== launch ====================
extern "C" void kernel_launch(void* const* d_in, const int* in_sizes, int n_in,
                              void* d_out, int out_size) {
    const float* x       = (const float*)d_in[0];
    const float* anchors = (const float*)d_in[1];
    const float* W1      = (const float*)d_in[2];
    const float* b1      = (const float*)d_in[3];
    const float* W2      = (const float*)d_in[4];
    const float* b2      = (const float*)d_in[5];
    float* out = (float*)d_out;

    static int attr_done = 0;
    if (!attr_done) {
        cudaFuncSetAttribute(k_gemm1, cudaFuncAttributeMaxDynamicSharedMemorySize, SMEM_DYN);
        cudaFuncSetAttribute(k_gemm2, cudaFuncAttributeMaxDynamicSharedMemorySize, SMEM_DYN);
        attr_done = 1;
    }

    const int OUT_END = T_TOK * DIM;
    const int AN_END  = OUT_END + NEXP * DIM;
    const int SC_END  = AN_END + T_TOK * NEXP;
    const int IX_END  = SC_END + T_TOK * 2;
    int write_an = (out_size >= AN_END) ? 1 : 0;
    int wflags = ((out_size >= SC_END) ? 1 : 0) | ((out_size >= IX_END) ? 2 : 0);

    k_anchors<<<1, 256>>>(anchors, out + OUT_END, write_an);
    k_route<<<512, 256>>>(x, out, out + AN_END, out + SC_END, wflags);
    dim3 gx(T_TOK / TM, NEXP);
    k_xpose<<<gx, 128>>>();
    dim3 g1(FDIM / TN, T_TOK / TM, NEXP);
    k_gemm1<<<g1, NTHREADS, SMEM_DYN>>>(x, W1, b1);
    dim3 g2((DIM / TN) * 2, T_TOK / TM, NEXP);
    k_gemm2<<<g2, NTHREADS, SMEM_DYN>>>(W2, b2, out);
}